// round 11
// baseline (speedup 1.0000x reference)
#include <cuda_runtime.h>
#include <cuda_fp16.h>
#include <math.h>

#define S_LEN   2048
#define DIMV    2048
#define KVD     512
#define NQH     16
#define NKVH    4
#define HDM     128
#define SCALE   0.08838834764831845f   // 1/sqrt(128)

// ---- scratch (no cudaMalloc allowed) ----
__device__ __half h_query[S_LEN * DIMV];
__device__ __half h_key[S_LEN * DIMV];
__device__ __half h_value[S_LEN * DIMV];
__device__ __half h_Wq[DIMV * DIMV];     // pre-scaled by SCALE
__device__ __half h_Wk[KVD * DIMV];
__device__ __half h_Wv[KVD * DIMV];
__device__ __half h_Wo[DIMV * DIMV];
__device__ __half g_Qh[S_LEN * DIMV];
__device__ __half g_Kh[S_LEN * KVD];
__device__ __half g_Vh[S_LEN * KVD];
__device__ __half g_Oh[S_LEN * DIMV];
__device__ float2 g_rope[S_LEN * 64];    // (cos, sin) table

// ============================================================
// helpers
// ============================================================
__device__ __forceinline__ void mma_f16(float* c, const unsigned* a, const unsigned* b) {
    asm volatile(
        "mma.sync.aligned.m16n8k16.row.col.f32.f16.f16.f32 "
        "{%0,%1,%2,%3}, {%4,%5,%6,%7}, {%8,%9}, {%0,%1,%2,%3};"
        : "+f"(c[0]), "+f"(c[1]), "+f"(c[2]), "+f"(c[3])
        : "r"(a[0]), "r"(a[1]), "r"(a[2]), "r"(a[3]), "r"(b[0]), "r"(b[1]));
}

__device__ __forceinline__ void ldsm_x4(
    unsigned& r0, unsigned& r1, unsigned& r2, unsigned& r3, unsigned addr)
{
    asm volatile("ldmatrix.sync.aligned.m8n8.x4.shared.b16 {%0,%1,%2,%3}, [%4];"
        : "=r"(r0), "=r"(r1), "=r"(r2), "=r"(r3) : "r"(addr));
}

__device__ __forceinline__ void ldsm_x4_t(
    unsigned& r0, unsigned& r1, unsigned& r2, unsigned& r3, unsigned addr)
{
    asm volatile("ldmatrix.sync.aligned.m8n8.x4.trans.shared.b16 {%0,%1,%2,%3}, [%4];"
        : "=r"(r0), "=r"(r1), "=r"(r2), "=r"(r3) : "r"(addr));
}

__device__ __forceinline__ void cp16(unsigned dst, const void* src) {
    asm volatile("cp.async.cg.shared.global [%0], [%1], 16;" :: "r"(dst), "l"(src));
}
__device__ __forceinline__ void cp_commit() {
    asm volatile("cp.async.commit_group;");
}
__device__ __forceinline__ void cp_wait0() {
    asm volatile("cp.async.wait_group 0;" ::: "memory");
}

// ============================================================
// fused fp32 -> fp16 convert of all inputs (Wq scaled by SCALE)
// ============================================================
#define N4_BIG ((S_LEN * DIMV) / 4)
#define N4_SM  ((KVD * DIMV) / 4)
#define N4_TOT (5 * N4_BIG + 2 * N4_SM)

__global__ void __launch_bounds__(256) cvt_all_kernel(
    const float4* __restrict__ q, const float4* __restrict__ k,
    const float4* __restrict__ v, const float4* __restrict__ wq,
    const float4* __restrict__ wo, const float4* __restrict__ wk,
    const float4* __restrict__ wv)
{
    int i = blockIdx.x * blockDim.x + threadIdx.x;
    if (i >= N4_TOT) return;
    const float4* src;
    __half2* dst;
    float s = 1.0f;
    int off;
    if (i < N4_BIG)           { src = q;  dst = (__half2*)h_query; off = i; }
    else if (i < 2 * N4_BIG)  { src = k;  dst = (__half2*)h_key;   off = i - N4_BIG; }
    else if (i < 3 * N4_BIG)  { src = v;  dst = (__half2*)h_value; off = i - 2 * N4_BIG; }
    else if (i < 4 * N4_BIG)  { src = wq; dst = (__half2*)h_Wq;    off = i - 3 * N4_BIG; s = SCALE; }
    else if (i < 5 * N4_BIG)  { src = wo; dst = (__half2*)h_Wo;    off = i - 4 * N4_BIG; }
    else if (i < 5 * N4_BIG + N4_SM) { src = wk; dst = (__half2*)h_Wk; off = i - 5 * N4_BIG; }
    else                      { src = wv; dst = (__half2*)h_Wv;    off = i - 5 * N4_BIG - N4_SM; }
    float4 val = src[off];
    dst[2 * off]     = __floats2half2_rn(val.x * s, val.y * s);
    dst[2 * off + 1] = __floats2half2_rn(val.z * s, val.w * s);
}

// ============================================================
// fp16 GEMM: C[m][n] = sum_k A[m][k]*B[n][k] + bscale*bias[n]
// BM=128, BN=128, BK=64 halves, 3-stage cp.async,
// 256 thr / 8 warps (2x4), warp tile 64x32, mma.m16n8k16,
// ldmatrix fragment loads. Smem rows stride 72 halves.
// smem 110592 B -> 2 CTAs/SM; acc 64 regs -> <=128 regs/thread.
// K fixed 2048.
// ============================================================
#define GKH    2048
#define HSTR   72
#define GA_B   18432               // A region bytes (128*72*2)
#define GSTG_B 36864               // stage bytes (A + B, each 128 rows)
#define G_SMEM (3 * GSTG_B)        // 110592

// per-thread: 4 A cp16 + 4 B cp16. row = tid>>1 (0..127), segs (tid&1)*4..+3
__device__ __forceinline__ void g_issue_h(
    const __half* ag, const __half* bg, unsigned as_, unsigned bs_)
{
#pragma unroll
    for (int i = 0; i < 4; i++) {
        cp16(as_ + i * 16, ag + i * 8);
        cp16(bs_ + i * 16, bg + i * 8);
    }
    cp_commit();
}

template <bool HALF_OUT>
__device__ __forceinline__ void gemm_f16_body(
    const __half* __restrict__ A, const __half* __restrict__ B,
    const float* __restrict__ bias, float bscale, void* __restrict__ Cv,
    int N, int bm, int bn)
{
    extern __shared__ char smc[];
    unsigned smem_base = (unsigned)__cvta_generic_to_shared(smc);
    const int tid  = threadIdx.x;       // 256 threads
    const int lane = tid & 31;
    const int wid  = tid >> 5;          // 8 warps, 2x4
    const int lg   = lane >> 2;
    const int lc   = lane & 3;
    const int wm   = (wid >> 2) * 64;   // 0,64
    const int wn   = (wid & 3) * 32;    // 0..96

    const int a_mrow = lane & 15, a_kseg = lane >> 4;
    const int b_nrow = ((lane >> 4) << 3) + (lane & 7);
    const int b_kseg = (lane >> 3) & 1;

    const int grow = tid >> 1;          // 0..127
    const int gseg = (tid & 1) * 4;     // 16B segment base

    const __half* Ag = A + (bm + grow) * GKH + gseg * 8;
    const __half* Bg = B + (bn + grow) * GKH + gseg * 8;
    const unsigned aoff = (grow * HSTR + gseg * 8) * 2;
    const unsigned boff = GA_B + (grow * HSTR + gseg * 8) * 2;

    float acc[4][4][4];
#pragma unroll
    for (int mt = 0; mt < 4; mt++)
#pragma unroll
        for (int nt = 0; nt < 4; nt++)
#pragma unroll
            for (int c = 0; c < 4; c++) acc[mt][nt][c] = 0.f;

    g_issue_h(Ag,      Bg,      smem_base + aoff,          smem_base + boff);
    g_issue_h(Ag + 64, Bg + 64, smem_base + GSTG_B + aoff, smem_base + GSTG_B + boff);

    const int nIter = GKH / 64;   // 32
    for (int kt = 0; kt < nIter; kt++) {
        asm volatile("cp.async.wait_group 1;" ::: "memory");
        __syncthreads();
        if (kt + 2 < nIter) {
            int s = (kt + 2) % 3;
            g_issue_h(Ag + (kt + 2) * 64, Bg + (kt + 2) * 64,
                      smem_base + s * GSTG_B + aoff,
                      smem_base + s * GSTG_B + boff);
        } else {
            cp_commit();
        }

        const unsigned As_b = smem_base + (kt % 3) * GSTG_B;
        const unsigned Bs_b = As_b + GA_B;
#pragma unroll
        for (int ks = 0; ks < 4; ks++) {
            unsigned af[4][4], bf[4][2];
#pragma unroll
            for (int mt = 0; mt < 4; mt++)
                ldsm_x4(af[mt][0], af[mt][1], af[mt][2], af[mt][3],
                        As_b + ((wm + mt * 16 + a_mrow) * HSTR + ks * 16 + a_kseg * 8) * 2);
#pragma unroll
            for (int np = 0; np < 2; np++)
                ldsm_x4(bf[2 * np][0], bf[2 * np][1], bf[2 * np + 1][0], bf[2 * np + 1][1],
                        Bs_b + ((wn + np * 16 + b_nrow) * HSTR + ks * 16 + b_kseg * 8) * 2);
#pragma unroll
            for (int mt = 0; mt < 4; mt++)
#pragma unroll
                for (int nt = 0; nt < 4; nt++)
                    mma_f16(acc[mt][nt], af[mt], bf[nt]);
        }
    }

#pragma unroll
    for (int mt = 0; mt < 4; mt++) {
        int row = bm + wm + mt * 16 + lg;
#pragma unroll
        for (int nt = 0; nt < 4; nt++) {
            int col = bn + wn + nt * 8 + 2 * lc;
            float b0 = __ldg(bias + col)     * bscale;
            float b1 = __ldg(bias + col + 1) * bscale;
            float o0 = acc[mt][nt][0] + b0, o1 = acc[mt][nt][1] + b1;
            float o2 = acc[mt][nt][2] + b0, o3 = acc[mt][nt][3] + b1;
            if (HALF_OUT) {
                __half* C = (__half*)Cv;
                *(__half2*)(C + row * N + col)       = __floats2half2_rn(o0, o1);
                *(__half2*)(C + (row + 8) * N + col) = __floats2half2_rn(o2, o3);
            } else {
                float* C = (float*)Cv;
                *(float2*)(C + row * N + col)       = make_float2(o0, o1);
                *(float2*)(C + (row + 8) * N + col) = make_float2(o2, o3);
            }
        }
    }
}

// fused Q/K/V projection: blocks 0..255 Q (scaled), 256..319 K, 320..383 V
__global__ void __launch_bounds__(256, 2) proj_kernel(
    const float* __restrict__ bq, const float* __restrict__ bk,
    const float* __restrict__ bv)
{
    int b = blockIdx.x;
    if (b < 256) {
        gemm_f16_body<true>(h_query, h_Wq, bq, SCALE, g_Qh, DIMV,
                            (b >> 4) * 128, (b & 15) * 128);
    } else if (b < 320) {
        int i = b - 256;
        gemm_f16_body<true>(h_key, h_Wk, bk, 1.0f, g_Kh, KVD,
                            (i >> 2) * 128, (i & 3) * 128);
    } else {
        int i = b - 320;
        gemm_f16_body<true>(h_value, h_Wv, bv, 1.0f, g_Vh, KVD,
                            (i >> 2) * 128, (i & 3) * 128);
    }
}

__global__ void __launch_bounds__(256, 2) gemm_o_kernel(
    const float* __restrict__ bo, float* __restrict__ out)
{
    int b = blockIdx.x;
    gemm_f16_body<false>(g_Oh, h_Wo, bo, 1.0f, out, DIMV,
                         (b >> 4) * 128, (b & 15) * 128);
}

// ============================================================
// RoPE: table precompute + apply
// ============================================================
__global__ void __launch_bounds__(256) rope_tab_kernel()
{
    int idx = blockIdx.x * blockDim.x + threadIdx.x;
    if (idx >= S_LEN * 64) return;
    int j = idx & 63;
    int s = idx >> 6;
    float inv = powf(10000.0f, -(float)(2 * j) * (1.0f / 128.0f));
    float sn, cs;
    sincosf((float)s * inv, &sn, &cs);
    g_rope[idx] = make_float2(cs, sn);
}

__global__ void __launch_bounds__(256) rope_kernel()
{
    const int total = S_LEN * (NQH + NKVH) * 64;
    int idx = blockIdx.x * blockDim.x + threadIdx.x;
    if (idx >= total) return;
    int j  = idx & 63;
    int t  = idx >> 6;
    int hh = t % (NQH + NKVH);
    int s  = t / (NQH + NKVH);

    float2 cssn = g_rope[s * 64 + j];

    __half* base = (hh < NQH) ? (g_Qh + s * DIMV + hh * HDM)
                              : (g_Kh + s * KVD + (hh - NQH) * HDM);
    float x1 = __half2float(base[j]);
    float x2 = __half2float(base[j + 64]);
    base[j]      = __float2half_rn(x1 * cssn.x - x2 * cssn.y);
    base[j + 64] = __float2half_rn(x2 * cssn.x + x1 * cssn.y);
}

// ============================================================
// Flash attention, fp16 MMA + ldmatrix, causal GQA (R8, unchanged)
// ============================================================
#define AQ_B   0
#define AK_B   17408
#define AV_B   52224
#define ASP_B  87040
#define AM_B   96256
#define AL_B   96512
#define AS_B   96768
#define ATT_SMEM 97024
#define KVSTR  136
#define PSH    72

__device__ __forceinline__ void attn_issue_kv(
    const __half* Kb, const __half* Vb, int j, int buf,
    unsigned smem_base, int tid)
{
    const __half* Ksrc = Kb + (j * 64) * KVD;
    const __half* Vsrc = Vb + (j * 64) * KVD;
    unsigned kb = smem_base + AK_B + buf * 17408;
    unsigned vb = smem_base + AV_B + buf * 17408;
#pragma unroll
    for (int i = 0; i < 4; i++) {
        int c   = tid + i * 256;
        int row = c >> 4;
        int sg  = c & 15;
        cp16(kb + (row * KVSTR + sg * 8) * 2, Ksrc + row * KVD + sg * 8);
        cp16(vb + (row * KVSTR + sg * 8) * 2, Vsrc + row * KVD + sg * 8);
    }
    cp_commit();
}

__global__ void __launch_bounds__(256) attn_kernel()
{
    extern __shared__ char smc[];
    unsigned smem_base = (unsigned)__cvta_generic_to_shared(smc);
    float* sm = (float*)smc;

    const int tid  = threadIdx.x;
    const int lane = tid & 31;
    const int wid  = tid >> 5;
    const int qt   = gridDim.x - 1 - blockIdx.x;
    const int h    = blockIdx.y;
    const int kvh  = h >> 2;
    const int lg   = lane >> 2;
    const int lc   = lane & 3;

    const int a_mrow = lane & 15, a_kseg = lane >> 4;
    const int b_nrow = ((lane >> 4) << 3) + (lane & 7);
    const int b_kseg = (lane >> 3) & 1;

    const int wms = (wid >> 2) * 32;
    const int wns = (wid & 3) * 16;
    const int wmp = (wid >> 2) * 32;
    const int wnp = (wid & 3) * 32;

    const __half* Qb = g_Qh + h * HDM;
    const __half* Kb = g_Kh + kvh * HDM;
    const __half* Vb = g_Vh + kvh * HDM;

    attn_issue_kv(Kb, Vb, 0, 0, smem_base, tid);

    {
        const __half* Qsrc = Qb + (qt * 64) * DIMV;
#pragma unroll
        for (int i = 0; i < 4; i++) {
            int c   = tid + i * 256;
            int row = c >> 4;
            int sg  = c & 15;
            cp16(smem_base + AQ_B + (row * KVSTR + sg * 8) * 2,
                 Qsrc + row * DIMV + sg * 8);
        }
        cp_commit();
    }
    {
        float* mrow = (float*)(smc + AM_B);
        float* lrow = (float*)(smc + AL_B);
        if (tid < 64) { mrow[tid] = -1e30f; lrow[tid] = 0.f; }
    }
    cp_wait0();
    __syncthreads();

    unsigned qf[2][8][4];
#pragma unroll
    for (int mt = 0; mt < 2; mt++)
#pragma unroll
        for (int ks = 0; ks < 8; ks++)
            ldsm_x4(qf[mt][ks][0], qf[mt][ks][1], qf[mt][ks][2], qf[mt][ks][3],
                    smem_base + AQ_B +
                    ((wms + mt * 16 + a_mrow) * KVSTR + ks * 16 + a_kseg * 8) * 2);
    __syncthreads();

    float oacc[2][4][4];
#pragma unroll
    for (int mt = 0; mt < 2; mt++)
#pragma unroll
        for (int nt = 0; nt < 4; nt++)
#pragma unroll
            for (int c = 0; c < 4; c++) oacc[mt][nt][c] = 0.f;

    int buf = 0;
    for (int j = 0; j <= qt; j++) {
        if (j < qt) attn_issue_kv(Kb, Vb, j + 1, buf ^ 1, smem_base, tid);

        const unsigned kbase = smem_base + AK_B + buf * 17408;
        float sacc[2][2][4];
#pragma unroll
        for (int mt = 0; mt < 2; mt++)
#pragma unroll
            for (int nt = 0; nt < 2; nt++)
#pragma unroll
                for (int c = 0; c < 4; c++) sacc[mt][nt][c] = 0.f;

#pragma unroll
        for (int ks = 0; ks < 8; ks++) {
            unsigned bf[2][2];
            ldsm_x4(bf[0][0], bf[0][1], bf[1][0], bf[1][1],
                    kbase + ((wns + b_nrow) * KVSTR + ks * 16 + b_kseg * 8) * 2);
#pragma unroll
            for (int mt = 0; mt < 2; mt++)
#pragma unroll
                for (int nt = 0; nt < 2; nt++)
                    mma_f16(sacc[mt][nt], qf[mt][ks], bf[nt]);
        }

        float* sS = sm;
#pragma unroll
        for (int mt = 0; mt < 2; mt++) {
            int r0 = wms + mt * 16 + lg;
#pragma unroll
            for (int nt = 0; nt < 2; nt++) {
                int c0 = wns + nt * 8 + 2 * lc;
                *(float2*)(sS + r0 * 68 + c0) =
                    make_float2(sacc[mt][nt][0], sacc[mt][nt][1]);
                *(float2*)(sS + (r0 + 8) * 68 + c0) =
                    make_float2(sacc[mt][nt][2], sacc[mt][nt][3]);
            }
        }
        __syncthreads();

        {
            float* mrow = (float*)(smc + AM_B);
            float* lrow = (float*)(smc + AL_B);
            float* srow = (float*)(smc + AS_B);
            int row = tid >> 2;
            int q4  = tid & 3;
            float v[16];
            *(float4*)(v)      = *(const float4*)(sS + row * 68 + q4 * 16);
            *(float4*)(v + 4)  = *(const float4*)(sS + row * 68 + q4 * 16 + 4);
            *(float4*)(v + 8)  = *(const float4*)(sS + row * 68 + q4 * 16 + 8);
            *(float4*)(v + 12) = *(const float4*)(sS + row * 68 + q4 * 16 + 12);
            if (j == qt) {
#pragma unroll
                for (int i = 0; i < 16; i++)
                    if (q4 * 16 + i > row) v[i] = -1e30f;
            }
            float mo = mrow[row];
            float mx = v[0];
#pragma unroll
            for (int i = 1; i < 16; i++) mx = fmaxf(mx, v[i]);
            mx = fmaxf(mx, __shfl_xor_sync(0xffffffffu, mx, 1));
            mx = fmaxf(mx, __shfl_xor_sync(0xffffffffu, mx, 2));
            float mnew = fmaxf(mo, mx);
            float sum = 0.f;
            unsigned pw[8];
#pragma unroll
            for (int i = 0; i < 8; i++) {
                float p0 = __expf(v[2 * i]     - mnew);
                float p1 = __expf(v[2 * i + 1] - mnew);
                sum += p0 + p1;
                __half2 hp = __floats2half2_rn(p0, p1);
                pw[i] = *(unsigned*)&hp;
            }
            sum += __shfl_xor_sync(0xffffffffu, sum, 1);
            sum += __shfl_xor_sync(0xffffffffu, sum, 2);
            unsigned* sPw = (unsigned*)(smc + ASP_B);
            *(uint4*)(sPw + row * (PSH / 2) + q4 * 8)     = *(uint4*)(pw);
            *(uint4*)(sPw + row * (PSH / 2) + q4 * 8 + 4) = *(uint4*)(pw + 4);
            if (q4 == 0) {
                float esc = __expf(mo - mnew);
                mrow[row] = mnew;
                lrow[row] = lrow[row] * esc + sum;
                srow[row] = esc;
            }
        }
        __syncthreads();

        {
            const float* srow = (const float*)(smc + AS_B);
#pragma unroll
            for (int mt = 0; mt < 2; mt++) {
                float e0 = srow[wmp + mt * 16 + lg];
                float e1 = srow[wmp + mt * 16 + lg + 8];
#pragma unroll
                for (int nt = 0; nt < 4; nt++) {
                    oacc[mt][nt][0] *= e0;
                    oacc[mt][nt][1] *= e0;
                    oacc[mt][nt][2] *= e1;
                    oacc[mt][nt][3] *= e1;
                }
            }
        }
        {
            const unsigned pbase = smem_base + ASP_B;
            const unsigned vbase = smem_base + AV_B + buf * 17408;
            const int seg = lane >> 3, r = lane & 7;
#pragma unroll
            for (int ks = 0; ks < 4; ks++) {
                unsigned af[2][4];
#pragma unroll
                for (int mt = 0; mt < 2; mt++)
                    ldsm_x4(af[mt][0], af[mt][1], af[mt][2], af[mt][3],
                            pbase + ((wmp + mt * 16 + a_mrow) * PSH + ks * 16 + a_kseg * 8) * 2);
                unsigned bv[4][2];
#pragma unroll
                for (int p = 0; p < 2; p++) {
                    int row = ks * 16 + (seg & 1) * 8 + r;
                    int col = wnp + p * 16 + (seg >> 1) * 8;
                    ldsm_x4_t(bv[2 * p][0], bv[2 * p][1],
                              bv[2 * p + 1][0], bv[2 * p + 1][1],
                              vbase + (row * KVSTR + col) * 2);
                }
#pragma unroll
                for (int mt = 0; mt < 2; mt++)
#pragma unroll
                    for (int nt = 0; nt < 4; nt++)
                        mma_f16(oacc[mt][nt], af[mt], bv[nt]);
            }
        }
        cp_wait0();
        __syncthreads();
        buf ^= 1;
    }

    {
        const float* lrow = (const float*)(smc + AL_B);
#pragma unroll
        for (int mt = 0; mt < 2; mt++) {
            int r  = wmp + mt * 16 + lg;
            float il0 = 1.0f / lrow[r];
            float il1 = 1.0f / lrow[r + 8];
            int gr = qt * 64 + r;
#pragma unroll
            for (int nt = 0; nt < 4; nt++) {
                int col = h * HDM + wnp + nt * 8 + 2 * lc;
                *(__half2*)(g_Oh + gr * DIMV + col) =
                    __floats2half2_rn(oacc[mt][nt][0] * il0, oacc[mt][nt][1] * il0);
                *(__half2*)(g_Oh + (gr + 8) * DIMV + col) =
                    __floats2half2_rn(oacc[mt][nt][2] * il1, oacc[mt][nt][3] * il1);
            }
        }
    }
}

// ============================================================
// launch
// ============================================================
extern "C" void kernel_launch(void* const* d_in, const int* in_sizes, int n_in,
                              void* d_out, int out_size)
{
    const float* query = (const float*)d_in[0];
    const float* key   = (const float*)d_in[1];
    const float* value = (const float*)d_in[2];
    const float* Wq    = (const float*)d_in[3];
    const float* bq    = (const float*)d_in[4];
    const float* Wk    = (const float*)d_in[5];
    const float* bk    = (const float*)d_in[6];
    const float* Wv    = (const float*)d_in[7];
    const float* bv    = (const float*)d_in[8];
    const float* Wo    = (const float*)d_in[9];
    const float* bo    = (const float*)d_in[10];
    float* out = (float*)d_out;

    cudaFuncSetAttribute((const void*)proj_kernel,
                         cudaFuncAttributeMaxDynamicSharedMemorySize, G_SMEM);
    cudaFuncSetAttribute((const void*)gemm_o_kernel,
                         cudaFuncAttributeMaxDynamicSharedMemorySize, G_SMEM);
    cudaFuncSetAttribute((const void*)attn_kernel,
                         cudaFuncAttributeMaxDynamicSharedMemorySize, ATT_SMEM);

    cvt_all_kernel<<<(N4_TOT + 255) / 256, 256>>>(
        (const float4*)query, (const float4*)key, (const float4*)value,
        (const float4*)Wq, (const float4*)Wo, (const float4*)Wk, (const float4*)Wv);

    rope_tab_kernel<<<(S_LEN * 64 + 255) / 256, 256>>>();

    proj_kernel<<<384, 256, G_SMEM>>>(bq, bk, bv);

    {
        const int total = S_LEN * (NQH + NKVH) * 64;
        rope_kernel<<<(total + 255) / 256, 256>>>();
    }

    attn_kernel<<<dim3(32, 16), 256, ATT_SMEM>>>();

    gemm_o_kernel<<<256, 256, G_SMEM>>>(bo, out);
}

// round 12
// speedup vs baseline: 1.1523x; 1.1523x over previous
#include <cuda_runtime.h>
#include <cuda_fp16.h>
#include <math.h>

#define S_LEN   2048
#define DIMV    2048
#define KVD     512
#define NQH     16
#define NKVH    4
#define HDM     128
#define SCALE   0.08838834764831845f   // 1/sqrt(128)

// ---- scratch (no cudaMalloc allowed) ----
__device__ __half h_query[S_LEN * DIMV];
__device__ __half h_key[S_LEN * DIMV];
__device__ __half h_value[S_LEN * DIMV];
__device__ __half h_Wq[DIMV * DIMV];     // pre-scaled by SCALE
__device__ __half h_Wk[KVD * DIMV];
__device__ __half h_Wv[KVD * DIMV];
__device__ __half h_Wo[DIMV * DIMV];
__device__ __half g_Qh[S_LEN * DIMV];
__device__ __half g_Kh[S_LEN * KVD];
__device__ __half g_Vh[S_LEN * KVD];
__device__ __half g_Oh[S_LEN * DIMV];
__device__ float2 g_rope[S_LEN * 64];    // (cos, sin) table

// ============================================================
// helpers
// ============================================================
__device__ __forceinline__ void mma_f16(float* c, const unsigned* a, const unsigned* b) {
    asm volatile(
        "mma.sync.aligned.m16n8k16.row.col.f32.f16.f16.f32 "
        "{%0,%1,%2,%3}, {%4,%5,%6,%7}, {%8,%9}, {%0,%1,%2,%3};"
        : "+f"(c[0]), "+f"(c[1]), "+f"(c[2]), "+f"(c[3])
        : "r"(a[0]), "r"(a[1]), "r"(a[2]), "r"(a[3]), "r"(b[0]), "r"(b[1]));
}

__device__ __forceinline__ void ldsm_x4(
    unsigned& r0, unsigned& r1, unsigned& r2, unsigned& r3, unsigned addr)
{
    asm volatile("ldmatrix.sync.aligned.m8n8.x4.shared.b16 {%0,%1,%2,%3}, [%4];"
        : "=r"(r0), "=r"(r1), "=r"(r2), "=r"(r3) : "r"(addr));
}

__device__ __forceinline__ void ldsm_x4_t(
    unsigned& r0, unsigned& r1, unsigned& r2, unsigned& r3, unsigned addr)
{
    asm volatile("ldmatrix.sync.aligned.m8n8.x4.trans.shared.b16 {%0,%1,%2,%3}, [%4];"
        : "=r"(r0), "=r"(r1), "=r"(r2), "=r"(r3) : "r"(addr));
}

__device__ __forceinline__ void cp16(unsigned dst, const void* src) {
    asm volatile("cp.async.cg.shared.global [%0], [%1], 16;" :: "r"(dst), "l"(src));
}
__device__ __forceinline__ void cp_commit() {
    asm volatile("cp.async.commit_group;");
}
__device__ __forceinline__ void cp_wait0() {
    asm volatile("cp.async.wait_group 0;" ::: "memory");
}

// ============================================================
// fused fp32 -> fp16 convert of all inputs (Wq scaled by SCALE)
// ============================================================
#define N4_BIG ((S_LEN * DIMV) / 4)
#define N4_SM  ((KVD * DIMV) / 4)
#define N4_TOT (5 * N4_BIG + 2 * N4_SM)

__global__ void __launch_bounds__(256) cvt_all_kernel(
    const float4* __restrict__ q, const float4* __restrict__ k,
    const float4* __restrict__ v, const float4* __restrict__ wq,
    const float4* __restrict__ wo, const float4* __restrict__ wk,
    const float4* __restrict__ wv)
{
    int i = blockIdx.x * blockDim.x + threadIdx.x;
    if (i >= N4_TOT) return;
    const float4* src;
    __half2* dst;
    float s = 1.0f;
    int off;
    if (i < N4_BIG)           { src = q;  dst = (__half2*)h_query; off = i; }
    else if (i < 2 * N4_BIG)  { src = k;  dst = (__half2*)h_key;   off = i - N4_BIG; }
    else if (i < 3 * N4_BIG)  { src = v;  dst = (__half2*)h_value; off = i - 2 * N4_BIG; }
    else if (i < 4 * N4_BIG)  { src = wq; dst = (__half2*)h_Wq;    off = i - 3 * N4_BIG; s = SCALE; }
    else if (i < 5 * N4_BIG)  { src = wo; dst = (__half2*)h_Wo;    off = i - 4 * N4_BIG; }
    else if (i < 5 * N4_BIG + N4_SM) { src = wk; dst = (__half2*)h_Wk; off = i - 5 * N4_BIG; }
    else                      { src = wv; dst = (__half2*)h_Wv;    off = i - 5 * N4_BIG - N4_SM; }
    float4 val = src[off];
    dst[2 * off]     = __floats2half2_rn(val.x * s, val.y * s);
    dst[2 * off + 1] = __floats2half2_rn(val.z * s, val.w * s);
}

// ============================================================
// fp16 GEMM (R8 config — DO NOT TOUCH):
// BM=128, BN=256, BK=64 halves, 3-stage cp.async, 256thr/8 warps,
// warp tile 64x64, mma.m16n8k16, ldmatrix. Smem stride 72 halves.
// ============================================================
#define GKH    2048
#define HSTR   72
#define GA_B   18432               // A region bytes (128*72*2)
#define GSTG_B 55296               // stage bytes
#define G_SMEM (3 * GSTG_B)        // 165888

__device__ __forceinline__ void g_issue_h(
    const __half* ag, const __half* bg, unsigned as_, unsigned bs_)
{
#pragma unroll
    for (int i = 0; i < 4; i++)
        cp16(as_ + i * 32 * HSTR * 2, ag + i * 32 * GKH);
#pragma unroll
    for (int i = 0; i < 8; i++)
        cp16(bs_ + i * 32 * HSTR * 2, bg + i * 32 * GKH);
    cp_commit();
}

template <bool HALF_OUT>
__device__ __forceinline__ void gemm_f16_body(
    const __half* __restrict__ A, const __half* __restrict__ B,
    const float* __restrict__ bias, float bscale, void* __restrict__ Cv,
    int N, int bm, int bn)
{
    extern __shared__ char smc[];
    unsigned smem_base = (unsigned)__cvta_generic_to_shared(smc);
    const int tid  = threadIdx.x;
    const int lane = tid & 31;
    const int wid  = tid >> 5;
    const int lg   = lane >> 2;
    const int lc   = lane & 3;
    const int wm   = (wid >> 2) * 64;
    const int wn   = (wid & 3) * 64;

    const int a_mrow = lane & 15, a_kseg = lane >> 4;
    const int b_nrow = ((lane >> 4) << 3) + (lane & 7);
    const int b_kseg = (lane >> 3) & 1;

    const int rowb = tid >> 3;
    const int seg  = tid & 7;

    const __half* Ag = A + (bm + rowb) * GKH + seg * 8;
    const __half* Bg = B + (bn + rowb) * GKH + seg * 8;
    const unsigned aoff = (rowb * HSTR + seg * 8) * 2;
    const unsigned boff = GA_B + (rowb * HSTR + seg * 8) * 2;

    float acc[4][8][4];
#pragma unroll
    for (int mt = 0; mt < 4; mt++)
#pragma unroll
        for (int nt = 0; nt < 8; nt++)
#pragma unroll
            for (int c = 0; c < 4; c++) acc[mt][nt][c] = 0.f;

    g_issue_h(Ag,      Bg,      smem_base + aoff,          smem_base + boff);
    g_issue_h(Ag + 64, Bg + 64, smem_base + GSTG_B + aoff, smem_base + GSTG_B + boff);

    const int nIter = GKH / 64;   // 32
    for (int kt = 0; kt < nIter; kt++) {
        asm volatile("cp.async.wait_group 1;" ::: "memory");
        __syncthreads();
        if (kt + 2 < nIter) {
            int s = (kt + 2) % 3;
            g_issue_h(Ag + (kt + 2) * 64, Bg + (kt + 2) * 64,
                      smem_base + s * GSTG_B + aoff,
                      smem_base + s * GSTG_B + boff);
        } else {
            cp_commit();
        }

        const unsigned As_b = smem_base + (kt % 3) * GSTG_B;
        const unsigned Bs_b = As_b + GA_B;
#pragma unroll
        for (int ks = 0; ks < 4; ks++) {
            unsigned af[4][4], bf[8][2];
#pragma unroll
            for (int mt = 0; mt < 4; mt++)
                ldsm_x4(af[mt][0], af[mt][1], af[mt][2], af[mt][3],
                        As_b + ((wm + mt * 16 + a_mrow) * HSTR + ks * 16 + a_kseg * 8) * 2);
#pragma unroll
            for (int np = 0; np < 4; np++)
                ldsm_x4(bf[2 * np][0], bf[2 * np][1], bf[2 * np + 1][0], bf[2 * np + 1][1],
                        Bs_b + ((wn + np * 16 + b_nrow) * HSTR + ks * 16 + b_kseg * 8) * 2);
#pragma unroll
            for (int mt = 0; mt < 4; mt++)
#pragma unroll
                for (int nt = 0; nt < 8; nt++)
                    mma_f16(acc[mt][nt], af[mt], bf[nt]);
        }
    }

#pragma unroll
    for (int mt = 0; mt < 4; mt++) {
        int row = bm + wm + mt * 16 + lg;
#pragma unroll
        for (int nt = 0; nt < 8; nt++) {
            int col = bn + wn + nt * 8 + 2 * lc;
            float b0 = __ldg(bias + col)     * bscale;
            float b1 = __ldg(bias + col + 1) * bscale;
            float o0 = acc[mt][nt][0] + b0, o1 = acc[mt][nt][1] + b1;
            float o2 = acc[mt][nt][2] + b0, o3 = acc[mt][nt][3] + b1;
            if (HALF_OUT) {
                __half* C = (__half*)Cv;
                *(__half2*)(C + row * N + col)       = __floats2half2_rn(o0, o1);
                *(__half2*)(C + (row + 8) * N + col) = __floats2half2_rn(o2, o3);
            } else {
                float* C = (float*)Cv;
                *(float2*)(C + row * N + col)       = make_float2(o0, o1);
                *(float2*)(C + (row + 8) * N + col) = make_float2(o2, o3);
            }
        }
    }
}

// fused Q/K/V projection: blocks 0..127 Q (scaled), 128..159 K, 160..191 V
__global__ void __launch_bounds__(256) proj_kernel(
    const float* __restrict__ bq, const float* __restrict__ bk,
    const float* __restrict__ bv)
{
    int b = blockIdx.x;
    if (b < 128) {
        gemm_f16_body<true>(h_query, h_Wq, bq, SCALE, g_Qh, DIMV,
                            (b >> 3) * 128, (b & 7) * 256);
    } else if (b < 160) {
        int i = b - 128;
        gemm_f16_body<true>(h_key, h_Wk, bk, 1.0f, g_Kh, KVD,
                            (i >> 1) * 128, (i & 1) * 256);
    } else {
        int i = b - 160;
        gemm_f16_body<true>(h_value, h_Wv, bv, 1.0f, g_Vh, KVD,
                            (i >> 1) * 128, (i & 1) * 256);
    }
}

__global__ void __launch_bounds__(256) gemm_o_kernel(
    const float* __restrict__ bo, float* __restrict__ out)
{
    int b = blockIdx.x;
    gemm_f16_body<false>(g_Oh, h_Wo, bo, 1.0f, out, DIMV,
                         (b >> 3) * 128, (b & 7) * 256);
}

// ============================================================
// RoPE: table precompute + apply (one table read per (s,j2),
// reused across all 20 heads; __half2 I/O)
// ============================================================
__global__ void __launch_bounds__(256) rope_tab_kernel()
{
    int idx = blockIdx.x * blockDim.x + threadIdx.x;
    if (idx >= S_LEN * 64) return;
    int j = idx & 63;
    int s = idx >> 6;
    float inv = powf(10000.0f, -(float)(2 * j) * (1.0f / 128.0f));
    float sn, cs;
    sincosf((float)s * inv, &sn, &cs);
    g_rope[idx] = make_float2(cs, sn);
}

__global__ void __launch_bounds__(256) rope_kernel()
{
    int idx = blockIdx.x * blockDim.x + threadIdx.x;   // s*32 + j2
    if (idx >= S_LEN * 32) return;
    int j2 = idx & 31;
    int s  = idx >> 5;
    float2 c0 = g_rope[s * 64 + 2 * j2];
    float2 c1 = g_rope[s * 64 + 2 * j2 + 1];

    __half2* qb = (__half2*)(g_Qh + s * DIMV);
#pragma unroll
    for (int hh = 0; hh < NQH; hh++) {
        float2 a = __half22float2(qb[hh * 64 + j2]);
        float2 b = __half22float2(qb[hh * 64 + 32 + j2]);
        qb[hh * 64 + j2]      = __floats2half2_rn(a.x * c0.x - b.x * c0.y,
                                                  a.y * c1.x - b.y * c1.y);
        qb[hh * 64 + 32 + j2] = __floats2half2_rn(b.x * c0.x + a.x * c0.y,
                                                  b.y * c1.x + a.y * c1.y);
    }
    __half2* kb = (__half2*)(g_Kh + s * KVD);
#pragma unroll
    for (int hh = 0; hh < NKVH; hh++) {
        float2 a = __half22float2(kb[hh * 64 + j2]);
        float2 b = __half22float2(kb[hh * 64 + 32 + j2]);
        kb[hh * 64 + j2]      = __floats2half2_rn(a.x * c0.x - b.x * c0.y,
                                                  a.y * c1.x - b.y * c1.y);
        kb[hh * 64 + 32 + j2] = __floats2half2_rn(b.x * c0.x + a.x * c0.y,
                                                  b.y * c1.x + a.y * c1.y);
    }
}

// ============================================================
// Flash attention, fp16 MMA + ldmatrix, causal GQA.
// BM=BN=64, HD=128, 256 thr / 8 warps, 2 CTAs/SM.
// Q frags streamed from persistent smem (saves 64 regs/thread).
// Smem 114432 B/CTA -> 2 CTAs/SM fit the 228KB budget.
// ============================================================
#define AQ_B   0
#define AK_B   17408
#define AV_B   52224
#define ASS_B  87040
#define ASP_B  104448
#define AM_B   113664
#define AL_B   113920
#define AS_B   114176
#define ATT_SMEM 114432
#define KVSTR  136
#define PSH    72

__device__ __forceinline__ void attn_issue_kv(
    const __half* Kb, const __half* Vb, int j, int buf,
    unsigned smem_base, int tid)
{
    const __half* Ksrc = Kb + (j * 64) * KVD;
    const __half* Vsrc = Vb + (j * 64) * KVD;
    unsigned kb = smem_base + AK_B + buf * 17408;
    unsigned vb = smem_base + AV_B + buf * 17408;
#pragma unroll
    for (int i = 0; i < 4; i++) {
        int c   = tid + i * 256;
        int row = c >> 4;
        int sg  = c & 15;
        cp16(kb + (row * KVSTR + sg * 8) * 2, Ksrc + row * KVD + sg * 8);
        cp16(vb + (row * KVSTR + sg * 8) * 2, Vsrc + row * KVD + sg * 8);
    }
    cp_commit();
}

__global__ void __launch_bounds__(256, 2) attn_kernel()
{
    extern __shared__ char smc[];
    unsigned smem_base = (unsigned)__cvta_generic_to_shared(smc);

    const int tid  = threadIdx.x;
    const int lane = tid & 31;
    const int wid  = tid >> 5;
    const int qt   = gridDim.x - 1 - blockIdx.x;
    const int h    = blockIdx.y;
    const int kvh  = h >> 2;
    const int lg   = lane >> 2;
    const int lc   = lane & 3;

    const int a_mrow = lane & 15, a_kseg = lane >> 4;
    const int b_nrow = ((lane >> 4) << 3) + (lane & 7);
    const int b_kseg = (lane >> 3) & 1;

    const int wms = (wid >> 2) * 32;
    const int wns = (wid & 3) * 16;
    const int wmp = (wid >> 2) * 32;
    const int wnp = (wid & 3) * 32;

    const __half* Qb = g_Qh + h * HDM;
    const __half* Kb = g_Kh + kvh * HDM;
    const __half* Vb = g_Vh + kvh * HDM;

    attn_issue_kv(Kb, Vb, 0, 0, smem_base, tid);

    {
        const __half* Qsrc = Qb + (qt * 64) * DIMV;
#pragma unroll
        for (int i = 0; i < 4; i++) {
            int c   = tid + i * 256;
            int row = c >> 4;
            int sg  = c & 15;
            cp16(smem_base + AQ_B + (row * KVSTR + sg * 8) * 2,
                 Qsrc + row * DIMV + sg * 8);
        }
        cp_commit();
    }
    {
        float* mrow = (float*)(smc + AM_B);
        float* lrow = (float*)(smc + AL_B);
        if (tid < 64) { mrow[tid] = -1e30f; lrow[tid] = 0.f; }
    }
    cp_wait0();
    __syncthreads();

    float oacc[2][4][4];
#pragma unroll
    for (int mt = 0; mt < 2; mt++)
#pragma unroll
        for (int nt = 0; nt < 4; nt++)
#pragma unroll
            for (int c = 0; c < 4; c++) oacc[mt][nt][c] = 0.f;

    const unsigned qbase = smem_base + AQ_B;
    int buf = 0;
    for (int j = 0; j <= qt; j++) {
        if (j < qt) attn_issue_kv(Kb, Vb, j + 1, buf ^ 1, smem_base, tid);

        // ---- S = Q K^T (Q frags streamed from persistent smem) ----
        const unsigned kbase = smem_base + AK_B + buf * 17408;
        float sacc[2][2][4];
#pragma unroll
        for (int mt = 0; mt < 2; mt++)
#pragma unroll
            for (int nt = 0; nt < 2; nt++)
#pragma unroll
                for (int c = 0; c < 4; c++) sacc[mt][nt][c] = 0.f;

#pragma unroll
        for (int ks = 0; ks < 8; ks++) {
            unsigned aq[2][4], bf[2][2];
#pragma unroll
            for (int mt = 0; mt < 2; mt++)
                ldsm_x4(aq[mt][0], aq[mt][1], aq[mt][2], aq[mt][3],
                        qbase + ((wms + mt * 16 + a_mrow) * KVSTR + ks * 16 + a_kseg * 8) * 2);
            ldsm_x4(bf[0][0], bf[0][1], bf[1][0], bf[1][1],
                    kbase + ((wns + b_nrow) * KVSTR + ks * 16 + b_kseg * 8) * 2);
#pragma unroll
            for (int mt = 0; mt < 2; mt++)
#pragma unroll
                for (int nt = 0; nt < 2; nt++)
                    mma_f16(sacc[mt][nt], aq[mt], bf[nt]);
        }

        float* sS = (float*)(smc + ASS_B);
#pragma unroll
        for (int mt = 0; mt < 2; mt++) {
            int r0 = wms + mt * 16 + lg;
#pragma unroll
            for (int nt = 0; nt < 2; nt++) {
                int c0 = wns + nt * 8 + 2 * lc;
                *(float2*)(sS + r0 * 68 + c0) =
                    make_float2(sacc[mt][nt][0], sacc[mt][nt][1]);
                *(float2*)(sS + (r0 + 8) * 68 + c0) =
                    make_float2(sacc[mt][nt][2], sacc[mt][nt][3]);
            }
        }
        __syncthreads();

        // ---- online softmax (4 threads per row) ----
        {
            float* mrow = (float*)(smc + AM_B);
            float* lrow = (float*)(smc + AL_B);
            float* srow = (float*)(smc + AS_B);
            int row = tid >> 2;
            int q4  = tid & 3;
            float v[16];
            *(float4*)(v)      = *(const float4*)(sS + row * 68 + q4 * 16);
            *(float4*)(v + 4)  = *(const float4*)(sS + row * 68 + q4 * 16 + 4);
            *(float4*)(v + 8)  = *(const float4*)(sS + row * 68 + q4 * 16 + 8);
            *(float4*)(v + 12) = *(const float4*)(sS + row * 68 + q4 * 16 + 12);
            if (j == qt) {
#pragma unroll
                for (int i = 0; i < 16; i++)
                    if (q4 * 16 + i > row) v[i] = -1e30f;
            }
            float mo = mrow[row];
            float mx = v[0];
#pragma unroll
            for (int i = 1; i < 16; i++) mx = fmaxf(mx, v[i]);
            mx = fmaxf(mx, __shfl_xor_sync(0xffffffffu, mx, 1));
            mx = fmaxf(mx, __shfl_xor_sync(0xffffffffu, mx, 2));
            float mnew = fmaxf(mo, mx);
            float sum = 0.f;
            unsigned pw[8];
#pragma unroll
            for (int i = 0; i < 8; i++) {
                float p0 = __expf(v[2 * i]     - mnew);
                float p1 = __expf(v[2 * i + 1] - mnew);
                sum += p0 + p1;
                __half2 hp = __floats2half2_rn(p0, p1);
                pw[i] = *(unsigned*)&hp;
            }
            sum += __shfl_xor_sync(0xffffffffu, sum, 1);
            sum += __shfl_xor_sync(0xffffffffu, sum, 2);
            unsigned* sPw = (unsigned*)(smc + ASP_B);
            *(uint4*)(sPw + row * (PSH / 2) + q4 * 8)     = *(uint4*)(pw);
            *(uint4*)(sPw + row * (PSH / 2) + q4 * 8 + 4) = *(uint4*)(pw + 4);
            if (q4 == 0) {
                float esc = __expf(mo - mnew);
                mrow[row] = mnew;
                lrow[row] = lrow[row] * esc + sum;
                srow[row] = esc;
            }
        }
        __syncthreads();

        // ---- rescale O, then O += P V ----
        {
            const float* srow = (const float*)(smc + AS_B);
#pragma unroll
            for (int mt = 0; mt < 2; mt++) {
                float e0 = srow[wmp + mt * 16 + lg];
                float e1 = srow[wmp + mt * 16 + lg + 8];
#pragma unroll
                for (int nt = 0; nt < 4; nt++) {
                    oacc[mt][nt][0] *= e0;
                    oacc[mt][nt][1] *= e0;
                    oacc[mt][nt][2] *= e1;
                    oacc[mt][nt][3] *= e1;
                }
            }
        }
        {
            const unsigned pbase = smem_base + ASP_B;
            const unsigned vbase = smem_base + AV_B + buf * 17408;
            const int seg = lane >> 3, r = lane & 7;
#pragma unroll
            for (int ks = 0; ks < 4; ks++) {
                unsigned af[2][4];
#pragma unroll
                for (int mt = 0; mt < 2; mt++)
                    ldsm_x4(af[mt][0], af[mt][1], af[mt][2], af[mt][3],
                            pbase + ((wmp + mt * 16 + a_mrow) * PSH + ks * 16 + a_kseg * 8) * 2);
                unsigned bv[4][2];
#pragma unroll
                for (int p = 0; p < 2; p++) {
                    int row = ks * 16 + (seg & 1) * 8 + r;
                    int col = wnp + p * 16 + (seg >> 1) * 8;
                    ldsm_x4_t(bv[2 * p][0], bv[2 * p][1],
                              bv[2 * p + 1][0], bv[2 * p + 1][1],
                              vbase + (row * KVSTR + col) * 2);
                }
#pragma unroll
                for (int mt = 0; mt < 2; mt++)
#pragma unroll
                    for (int nt = 0; nt < 4; nt++)
                        mma_f16(oacc[mt][nt], af[mt], bv[nt]);
            }
        }
        cp_wait0();
        __syncthreads();
        buf ^= 1;
    }

    // ---- epilogue ----
    {
        const float* lrow = (const float*)(smc + AL_B);
#pragma unroll
        for (int mt = 0; mt < 2; mt++) {
            int r  = wmp + mt * 16 + lg;
            float il0 = 1.0f / lrow[r];
            float il1 = 1.0f / lrow[r + 8];
            int gr = qt * 64 + r;
#pragma unroll
            for (int nt = 0; nt < 4; nt++) {
                int col = h * HDM + wnp + nt * 8 + 2 * lc;
                *(__half2*)(g_Oh + gr * DIMV + col) =
                    __floats2half2_rn(oacc[mt][nt][0] * il0, oacc[mt][nt][1] * il0);
                *(__half2*)(g_Oh + (gr + 8) * DIMV + col) =
                    __floats2half2_rn(oacc[mt][nt][2] * il1, oacc[mt][nt][3] * il1);
            }
        }
    }
}

// ============================================================
// launch
// ============================================================
extern "C" void kernel_launch(void* const* d_in, const int* in_sizes, int n_in,
                              void* d_out, int out_size)
{
    const float* query = (const float*)d_in[0];
    const float* key   = (const float*)d_in[1];
    const float* value = (const float*)d_in[2];
    const float* Wq    = (const float*)d_in[3];
    const float* bq    = (const float*)d_in[4];
    const float* Wk    = (const float*)d_in[5];
    const float* bk    = (const float*)d_in[6];
    const float* Wv    = (const float*)d_in[7];
    const float* bv    = (const float*)d_in[8];
    const float* Wo    = (const float*)d_in[9];
    const float* bo    = (const float*)d_in[10];
    float* out = (float*)d_out;

    cudaFuncSetAttribute((const void*)proj_kernel,
                         cudaFuncAttributeMaxDynamicSharedMemorySize, G_SMEM);
    cudaFuncSetAttribute((const void*)gemm_o_kernel,
                         cudaFuncAttributeMaxDynamicSharedMemorySize, G_SMEM);
    cudaFuncSetAttribute((const void*)attn_kernel,
                         cudaFuncAttributeMaxDynamicSharedMemorySize, ATT_SMEM);

    cvt_all_kernel<<<(N4_TOT + 255) / 256, 256>>>(
        (const float4*)query, (const float4*)key, (const float4*)value,
        (const float4*)Wq, (const float4*)Wo, (const float4*)Wk, (const float4*)Wv);

    rope_tab_kernel<<<(S_LEN * 64 + 255) / 256, 256>>>();

    proj_kernel<<<192, 256, G_SMEM>>>(bq, bk, bv);

    rope_kernel<<<(S_LEN * 32 + 255) / 256, 256>>>();

    attn_kernel<<<dim3(32, 16), 256, ATT_SMEM>>>();

    gemm_o_kernel<<<128, 256, G_SMEM>>>(bo, out);
}